// round 12
// baseline (speedup 1.0000x reference)
#include <cuda_runtime.h>
#include <cuda_bf16.h>
#include <math.h>
#include <stdint.h>

// Problem dims
#define BSZ     2
#define LSEQ    2048
#define DMODEL  2048
#define INTER   4096
#define NHEADS  64
#define PDIM    64
#define NSTATE  128
#define KCONV   4
#define CONV_DIM (INTER + 2*NSTATE)   // 4352
#define TOKENS  (BSZ*LSEQ)            // 4096
#define DTPAD   128
#define EPS     1e-5f

// Concatenated input-projection layout: [gate | xBC | dt]
#define NCAT    (INTER + CONV_DIM + DTPAD)   // 8576
#define XBC_OFF INTER                        // 4096
#define DT_OFF  (INTER + CONV_DIM)           // 8448

typedef unsigned long long u64;

// ---------------- scratch (device globals; no allocation allowed) ----------
__device__ __align__(16) float g_cat[TOKENS*NCAT];      // fused projections
__device__ __align__(16) float g_xBCc[TOKENS*CONV_DIM]; // post conv+silu
__device__ __align__(16) float g_y[TOKENS*INTER];
__device__ __align__(16) float2 g_spdA[TOKENS*NHEADS];  // (softplus, dA)

// split-bf16 operands for tensor-core GEMMs
__device__ __align__(16) __nv_bfloat16 g_hs_hi[TOKENS*DMODEL];
__device__ __align__(16) __nv_bfloat16 g_hs_lo[TOKENS*DMODEL];
__device__ __align__(16) __nv_bfloat16 g_Wcat_hi[NCAT*DMODEL];   // [Nconcat, K]
__device__ __align__(16) __nv_bfloat16 g_Wcat_lo[NCAT*DMODEL];
__device__ __align__(16) __nv_bfloat16 g_Wout_hi[DMODEL*INTER];
__device__ __align__(16) __nv_bfloat16 g_Wout_lo[DMODEL*INTER];
__device__ __align__(16) __nv_bfloat16 g_norm_hi[TOKENS*INTER];
__device__ __align__(16) __nv_bfloat16 g_norm_lo[TOKENS*INTER];

// ---------------- PTX helpers ----------------------------------------------
__device__ __forceinline__ uint32_t smem_u32(const void* p) {
    uint32_t a;
    asm("{ .reg .u64 t; cvta.to.shared.u64 t, %1; cvt.u32.u64 %0, t; }"
        : "=r"(a) : "l"(p));
    return a;
}
__device__ __forceinline__ void cp16(uint32_t dst, const void* src) {
    asm volatile("cp.async.cg.shared.global [%0], [%1], 16;"
                 :: "r"(dst), "l"(src) : "memory");
}
__device__ __forceinline__ void cp8(uint32_t dst, const void* src) {
    asm volatile("cp.async.ca.shared.global [%0], [%1], 8;"
                 :: "r"(dst), "l"(src) : "memory");
}
__device__ __forceinline__ void cp_commit() {
    asm volatile("cp.async.commit_group;" ::: "memory");
}
template<int PENDING>
__device__ __forceinline__ void cp_wait() {
    asm volatile("cp.async.wait_group %0;" :: "n"(PENDING) : "memory");
}
__device__ __forceinline__ void ldm_x4(uint32_t addr, uint32_t* r) {
    asm volatile("ldmatrix.sync.aligned.m8n8.x4.shared.b16 {%0,%1,%2,%3}, [%4];"
                 : "=r"(r[0]), "=r"(r[1]), "=r"(r[2]), "=r"(r[3]) : "r"(addr));
}
__device__ __forceinline__ void mma_bf16(float* c, const uint32_t* a, const uint32_t* b) {
    asm volatile(
        "mma.sync.aligned.m16n8k16.row.col.f32.bf16.bf16.f32 "
        "{%0,%1,%2,%3}, {%4,%5,%6,%7}, {%8,%9}, {%0,%1,%2,%3};"
        : "+f"(c[0]), "+f"(c[1]), "+f"(c[2]), "+f"(c[3])
        : "r"(a[0]), "r"(a[1]), "r"(a[2]), "r"(a[3]), "r"(b[0]), "r"(b[1]));
}
// Packed fp32x2 (Blackwell): two IEEE fp32 FMAs per issue.
__device__ __forceinline__ u64 fma2(u64 a, u64 b, u64 c) {
    u64 d;
    asm("fma.rn.f32x2 %0, %1, %2, %3;" : "=l"(d) : "l"(a), "l"(b), "l"(c));
    return d;
}
__device__ __forceinline__ u64 mul2(u64 a, u64 b) {
    u64 d;
    asm("mul.rn.f32x2 %0, %1, %2;" : "=l"(d) : "l"(a), "l"(b));
    return d;
}
__device__ __forceinline__ u64 pack2(float lo, float hi) {
    u64 d;
    asm("mov.b64 %0, {%1, %2};" : "=l"(d) : "f"(lo), "f"(hi));
    return d;
}
__device__ __forceinline__ void unpack2(float& lo, float& hi, u64 v) {
    asm("mov.b64 {%0, %1}, %2;" : "=f"(lo), "=f"(hi) : "l"(v));
}

// ---------------- HMMA GEMM: C[M,N] = A[M,K] @ Bt[N,K]^T -------------------
// BM=256, BN=128, BK=64; 8 warps, warp tile 64x64.
#define TB_A 32768
#define TB_B 16384
#define STAGE_SZ (2*TB_A + 2*TB_B)   // 98304 B
__global__ void __launch_bounds__(256) gemm_mma(
    const __nv_bfloat16* __restrict__ Ahi, const __nv_bfloat16* __restrict__ Alo,
    const __nv_bfloat16* __restrict__ Bhi, const __nv_bfloat16* __restrict__ Blo,
    float* __restrict__ C, int M, int N, int K)
{
    extern __shared__ char smem[];
    uint32_t sbase = smem_u32(smem);

    int tid = threadIdx.x;
    int lane = tid & 31, wid = tid >> 5;
    int wm = wid & 3, wn = wid >> 2;
    int brow = blockIdx.y * 256, bcol = blockIdx.x * 128;

    const __nv_bfloat16* srcA0 = Ahi + (size_t)brow * K;
    const __nv_bfloat16* srcA1 = Alo + (size_t)brow * K;
    const __nv_bfloat16* srcB0 = Bhi + (size_t)bcol * K;
    const __nv_bfloat16* srcB1 = Blo + (size_t)bcol * K;
    int nch = K >> 6;

    auto issue = [&](int ch) {
        uint32_t stage = sbase + (uint32_t)(ch & 1) * STAGE_SZ;
        #pragma unroll
        for (int t = 0; t < 2; t++) {
            const __nv_bfloat16* P = t ? srcA1 : srcA0;
            uint32_t tb = stage + (uint32_t)t * TB_A;
            #pragma unroll
            for (int i = 0; i < 8; i++) {
                int c = tid + i * 256;
                int row = c >> 3, u = c & 7;
                uint32_t dst = tb + (uint32_t)(row * 128 + ((u ^ (row & 7)) << 4));
                cp16(dst, P + (size_t)row * K + (size_t)ch * 64 + u * 8);
            }
        }
        #pragma unroll
        for (int t = 0; t < 2; t++) {
            const __nv_bfloat16* P = t ? srcB1 : srcB0;
            uint32_t tb = stage + 2 * TB_A + (uint32_t)t * TB_B;
            #pragma unroll
            for (int i = 0; i < 4; i++) {
                int c = tid + i * 256;
                int row = c >> 3, u = c & 7;
                uint32_t dst = tb + (uint32_t)(row * 128 + ((u ^ (row & 7)) << 4));
                cp16(dst, P + (size_t)row * K + (size_t)ch * 64 + u * 8);
            }
        }
        cp_commit();
    };

    float acc[4][8][4];
    #pragma unroll
    for (int mf = 0; mf < 4; mf++)
        #pragma unroll
        for (int nf = 0; nf < 8; nf++)
            #pragma unroll
            for (int j = 0; j < 4; j++) acc[mf][nf][j] = 0.f;

    issue(0);
    issue(1);

    for (int ch = 0; ch < nch; ch++) {
        if (ch + 1 < nch) cp_wait<1>(); else cp_wait<0>();
        __syncthreads();
        uint32_t stage = sbase + (uint32_t)(ch & 1) * STAGE_SZ;

        #pragma unroll
        for (int ks = 0; ks < 4; ks++) {
            uint32_t bH[8][2], bL[8][2];
            #pragma unroll
            for (int ng = 0; ng < 4; ng++) {
                int row = wn * 64 + ng * 16 + (lane & 7) + ((lane >> 4) & 1) * 8;
                int u   = ks * 2 + ((lane >> 3) & 1);
                uint32_t off = (uint32_t)(row * 128 + ((u ^ (row & 7)) << 4));
                uint32_t rH[4], rL[4];
                ldm_x4(stage + 2 * TB_A + off, rH);
                ldm_x4(stage + 2 * TB_A + TB_B + off, rL);
                bH[2*ng][0] = rH[0]; bH[2*ng][1] = rH[1];
                bH[2*ng+1][0] = rH[2]; bH[2*ng+1][1] = rH[3];
                bL[2*ng][0] = rL[0]; bL[2*ng][1] = rL[1];
                bL[2*ng+1][0] = rL[2]; bL[2*ng+1][1] = rL[3];
            }
            #pragma unroll
            for (int mf = 0; mf < 4; mf++) {
                int row = wm * 64 + mf * 16 + (lane & 7) + ((lane >> 3) & 1) * 8;
                int u   = ks * 2 + ((lane >> 4) & 1);
                uint32_t off = (uint32_t)(row * 128 + ((u ^ (row & 7)) << 4));
                uint32_t aH[4], aL[4];
                ldm_x4(stage + off, aH);
                ldm_x4(stage + TB_A + off, aL);
                #pragma unroll
                for (int nf = 0; nf < 8; nf++) {
                    mma_bf16(acc[mf][nf], aH, bH[nf]);
                    mma_bf16(acc[mf][nf], aH, bL[nf]);
                    mma_bf16(acc[mf][nf], aL, bH[nf]);
                }
            }
        }
        __syncthreads();
        if (ch + 2 < nch) issue(ch + 2);
    }

    #pragma unroll
    for (int mf = 0; mf < 4; mf++) {
        int row = brow + wm * 64 + mf * 16 + (lane >> 2);
        #pragma unroll
        for (int nf = 0; nf < 8; nf++) {
            int col = bcol + wn * 64 + nf * 8 + (lane & 3) * 2;
            *(float2*)&C[(size_t)row * N + col] =
                make_float2(acc[mf][nf][0], acc[mf][nf][1]);
            *(float2*)&C[(size_t)(row + 8) * N + col] =
                make_float2(acc[mf][nf][2], acc[mf][nf][3]);
        }
    }
}

// ---------------- fp32 -> (hi,lo) bf16 split, elementwise ------------------
__global__ void __launch_bounds__(256) split8_kernel(
    const float* __restrict__ x, __nv_bfloat16* __restrict__ hi,
    __nv_bfloat16* __restrict__ lo, int n)
{
    int i = (blockIdx.x * 256 + threadIdx.x) * 8;
    if (i >= n) return;
    float4 a = *(const float4*)(x + i);
    float4 b = *(const float4*)(x + i + 4);
    float v[8] = {a.x, a.y, a.z, a.w, b.x, b.y, b.z, b.w};
    uint32_t hp[4], lp[4];
    #pragma unroll
    for (int j = 0; j < 4; j++) {
        __nv_bfloat16 h0 = __float2bfloat16(v[2*j]);
        __nv_bfloat16 h1 = __float2bfloat16(v[2*j+1]);
        __nv_bfloat16 l0 = __float2bfloat16(v[2*j]   - __bfloat162float(h0));
        __nv_bfloat16 l1 = __float2bfloat16(v[2*j+1] - __bfloat162float(h1));
        __nv_bfloat162 hh = __halves2bfloat162(h0, h1);
        __nv_bfloat162 ll = __halves2bfloat162(l0, l1);
        hp[j] = *(uint32_t*)&hh;
        lp[j] = *(uint32_t*)&ll;
    }
    *(uint4*)(hi + i) = make_uint4(hp[0], hp[1], hp[2], hp[3]);
    *(uint4*)(lo + i) = make_uint4(lp[0], lp[1], lp[2], lp[3]);
}

// ---------------- W[K,N] -> Wt[N,K] with bf16 split ------------------------
__global__ void __launch_bounds__(256) transpose_split_kernel(
    const float* __restrict__ W, __nv_bfloat16* __restrict__ Thi,
    __nv_bfloat16* __restrict__ Tlo, int K, int N)
{
    __shared__ float tile[32][33];
    int k0 = blockIdx.y * 32, n0 = blockIdx.x * 32;
    int tx = threadIdx.x & 31, ty = threadIdx.x >> 5;
    #pragma unroll
    for (int j = ty; j < 32; j += 8)
        tile[j][tx] = W[(size_t)(k0 + j) * N + n0 + tx];
    __syncthreads();
    #pragma unroll
    for (int j = ty; j < 32; j += 8) {
        float v = tile[tx][j];
        __nv_bfloat16 h = __float2bfloat16(v);
        __nv_bfloat16 l = __float2bfloat16(v - __bfloat162float(h));
        size_t o = (size_t)(n0 + j) * K + k0 + tx;
        Thi[o] = h;
        Tlo[o] = l;
    }
}

// Padded variant: reads [K, Nsrc], writes [Npad, K] (rows >= Nsrc zero).
__global__ void __launch_bounds__(256) transpose_split_pad_kernel(
    const float* __restrict__ W, __nv_bfloat16* __restrict__ Thi,
    __nv_bfloat16* __restrict__ Tlo, int K, int Nsrc)
{
    __shared__ float tile[32][33];
    int k0 = blockIdx.y * 32, n0 = blockIdx.x * 32;
    int tx = threadIdx.x & 31, ty = threadIdx.x >> 5;
    #pragma unroll
    for (int j = ty; j < 32; j += 8)
        tile[j][tx] = (n0 + tx < Nsrc) ? W[(size_t)(k0 + j) * Nsrc + n0 + tx] : 0.f;
    __syncthreads();
    #pragma unroll
    for (int j = ty; j < 32; j += 8) {
        float v = tile[tx][j];
        __nv_bfloat16 h = __float2bfloat16(v);
        __nv_bfloat16 l = __float2bfloat16(v - __bfloat162float(h));
        size_t o = (size_t)(n0 + j) * K + k0 + tx;
        Thi[o] = h;
        Tlo[o] = l;
    }
}

// ---------------- causal depthwise conv1d (K=4) + bias + silu --------------
__global__ void __launch_bounds__(256) conv_silu_kernel(
    const float* __restrict__ conv_w, const float* __restrict__ conv_b)
{
    int idx = blockIdx.x * 256 + threadIdx.x;
    int c  = idx % CONV_DIM;
    int bt = idx / CONV_DIM;
    int t  = bt & (LSEQ - 1);
    float acc = conv_b[c];
    #pragma unroll
    for (int k = 0; k < KCONV; k++) {
        int tt = t - (KCONV - 1) + k;
        if (tt >= 0)
            acc = fmaf(g_cat[(size_t)(bt - (KCONV - 1) + k) * NCAT + XBC_OFF + c],
                       conv_w[c * KCONV + k], acc);
    }
    g_xBCc[idx] = acc / (1.f + __expf(-acc));
}

// ---------------- softplus/dA precompute: (t,h) -> (sp, dA) ---------------
__global__ void __launch_bounds__(256) spdA_kernel(
    const float* __restrict__ dt_bias, const float* __restrict__ A_log)
{
    int idx = blockIdx.x * 256 + threadIdx.x;     // over TOKENS*NHEADS
    int h  = idx & (NHEADS - 1);
    int bt = idx >> 6;
    float dtv = g_cat[(size_t)bt * NCAT + DT_OFF + h];
    float xdt = dtv + dt_bias[h];
    float sp  = (xdt < 10.f) ? __logf(1.f + __expf(xdt)) : xdt;
    float dA  = __expf(sp * (-__expf(A_log[h])));
    g_spdA[idx] = make_float2(sp, dA);
}

// ---------------- blocked SSM scan with packed f32x2 FMA -------------------
// One CTA per (b, head); 8 steps per barrier pair; double-buffered ring.
// State held as 16 packed fp32x2 pairs; B/C read as ulonglong2 (2 pairs).
__global__ void __launch_bounds__(256) scan_kernel(const float* __restrict__ Dvec)
{
    int b = blockIdx.x >> 6;
    int h = blockIdx.x & 63;
    int tid = threadIdx.x;
    int p = tid >> 2, q = tid & 3;
    u64 st2[16];
    #pragma unroll
    for (int i = 0; i < 16; i++) st2[i] = 0ull;
    const float Dh = Dvec[h];

    __shared__ __align__(16) float  sx[16][64];
    __shared__ __align__(16) float  sBC[16][256];
    __shared__ __align__(16) float2 sspdA[16];

    const float*  xbase  = g_xBCc + (size_t)b * LSEQ * CONV_DIM + h * PDIM;
    const float*  bcbase = g_xBCc + (size_t)b * LSEQ * CONV_DIM + INTER;
    const float2* pdA    = g_spdA + (size_t)b * LSEQ * NHEADS + h;
    float*        y_base = g_y    + (size_t)b * LSEQ * INTER + h * PDIM;

    auto issue_group = [&](int g) {
        int bt0 = g * 8;
        if (bt0 < LSEQ) {
            int half = (g & 1) * 8;
            #pragma unroll
            for (int it = 0; it < 3; it++) {
                int c = tid + it * 256;
                if (c < 640) {
                    int s = c / 80, ch = c % 80;
                    size_t off = (size_t)(bt0 + s) * CONV_DIM;
                    if (ch < 16)
                        cp16(smem_u32(&sx[half + s][ch * 4]), xbase + off + ch * 4);
                    else
                        cp16(smem_u32(&sBC[half + s][(ch - 16) * 4]),
                             bcbase + off + (ch - 16) * 4);
                }
            }
            if (tid < 8)
                cp8(smem_u32(&sspdA[half + tid]), pdA + (size_t)(bt0 + tid) * NHEADS);
        }
        cp_commit();
    };

    issue_group(0);
    issue_group(1);

    for (int g = 0; g < LSEQ / 8; g++) {
        cp_wait<1>();
        __syncthreads();
        int half = (g & 1) * 8;
        #pragma unroll
        for (int s = 0; s < 8; s++) {
            int slot = half + s;
            float2 sd = sspdA[slot];
            float sp = sd.x, dA = sd.y;
            float xv  = sx[slot][p];
            float dtx = sp * xv;
            u64 dA2  = pack2(dA, dA);
            u64 dtx2 = pack2(dtx, dtx);
            const ulonglong2* B2 = (const ulonglong2*)&sBC[slot][0];
            const ulonglong2* C2 = (const ulonglong2*)&sBC[slot][128];
            u64 a01 = 0ull, a23 = 0ull;
            #pragma unroll
            for (int j = 0; j < 8; j++) {
                ulonglong2 bv = B2[j * 4 + q];
                ulonglong2 cv = C2[j * 4 + q];
                u64 s0 = fma2(st2[2*j+0], dA2, mul2(dtx2, bv.x)); st2[2*j+0] = s0;
                u64 s1 = fma2(st2[2*j+1], dA2, mul2(dtx2, bv.y)); st2[2*j+1] = s1;
                a01 = fma2(s0, cv.x, a01);
                a23 = fma2(s1, cv.y, a23);
            }
            float l0, h0, l1, h1;
            unpack2(l0, h0, a01);
            unpack2(l1, h1, a23);
            float accv = (l0 + h0) + (l1 + h1);
            accv += __shfl_xor_sync(0xffffffffu, accv, 1);
            accv += __shfl_xor_sync(0xffffffffu, accv, 2);
            if (q == 0)
                y_base[(size_t)(g * 8 + s) * INTER + p] = fmaf(Dh, xv, accv);
        }
        __syncthreads();
        issue_group(g + 2);     // refills the half just consumed (post-barrier)
    }
}

// ---------------- gated RMSNorm + fused bf16 split -------------------------
__global__ void __launch_bounds__(256) norm_kernel(const float* __restrict__ norm_w)
{
    int tok = blockIdx.x;
    __shared__ float sh[INTER];
    __shared__ float sred[8];
    __shared__ float s_scale;
    const float* yrow = g_y   + (size_t)tok * INTER;
    const float* grow = g_cat + (size_t)tok * NCAT;      // gate at offset 0
    float ss = 0.f;
    for (int i = threadIdx.x; i < INTER; i += 256) {
        float g  = grow[i];
        float sg = g / (1.f + __expf(-g));
        float hh = yrow[i] * sg;
        sh[i] = hh;
        ss = fmaf(hh, hh, ss);
    }
    #pragma unroll
    for (int o = 16; o; o >>= 1) ss += __shfl_xor_sync(0xffffffffu, ss, o);
    if ((threadIdx.x & 31) == 0) sred[threadIdx.x >> 5] = ss;
    __syncthreads();
    if (threadIdx.x == 0) {
        float tot = 0.f;
        #pragma unroll
        for (int j = 0; j < 8; j++) tot += sred[j];
        s_scale = rsqrtf(tot * (1.f / INTER) + EPS);
    }
    __syncthreads();
    float r = s_scale;
    for (int i = threadIdx.x; i < INTER; i += 256) {
        float val = sh[i] * r * norm_w[i];
        __nv_bfloat16 h = __float2bfloat16(val);
        __nv_bfloat16 l = __float2bfloat16(val - __bfloat162float(h));
        size_t o = (size_t)tok * INTER + i;
        g_norm_hi[o] = h;
        g_norm_lo[o] = l;
    }
}

// ---------------- launch ---------------------------------------------------
extern "C" void kernel_launch(void* const* d_in, const int* in_sizes, int n_in,
                              void* d_out, int out_size)
{
    const float* hs      = (const float*)d_in[0];
    const float* W_z     = (const float*)d_in[1];
    const float* W_xBC   = (const float*)d_in[2];
    const float* W_dt    = (const float*)d_in[3];
    const float* conv_w  = (const float*)d_in[4];
    const float* conv_b  = (const float*)d_in[5];
    const float* dt_bias = (const float*)d_in[6];
    const float* A_log   = (const float*)d_in[7];
    const float* Dv      = (const float*)d_in[8];
    const float* norm_w  = (const float*)d_in[9];
    const float* W_out   = (const float*)d_in[10];
    float* out = (float*)d_out;

    float* p_cat;
    cudaGetSymbolAddress((void**)&p_cat, g_cat);
    __nv_bfloat16 *p_hs_hi, *p_hs_lo, *p_Wc_hi, *p_Wc_lo,
                  *p_Wo_hi, *p_Wo_lo, *p_nm_hi, *p_nm_lo;
    cudaGetSymbolAddress((void**)&p_hs_hi, g_hs_hi);
    cudaGetSymbolAddress((void**)&p_hs_lo, g_hs_lo);
    cudaGetSymbolAddress((void**)&p_Wc_hi, g_Wcat_hi);
    cudaGetSymbolAddress((void**)&p_Wc_lo, g_Wcat_lo);
    cudaGetSymbolAddress((void**)&p_Wo_hi, g_Wout_hi);
    cudaGetSymbolAddress((void**)&p_Wo_lo, g_Wout_lo);
    cudaGetSymbolAddress((void**)&p_nm_hi, g_norm_hi);
    cudaGetSymbolAddress((void**)&p_nm_lo, g_norm_lo);

    const int GSMEM = 2 * STAGE_SZ;   // 196608 B
    cudaFuncSetAttribute(gemm_mma, cudaFuncAttributeMaxDynamicSharedMemorySize, GSMEM);

    // 0) operand prep into one concatenated [NCAT, K] weight buffer
    split8_kernel<<<(TOKENS*DMODEL/8 + 255)/256, 256>>>(hs, p_hs_hi, p_hs_lo, TOKENS*DMODEL);
    transpose_split_kernel<<<dim3(INTER/32, DMODEL/32), 256>>>(
        W_z, p_Wc_hi, p_Wc_lo, DMODEL, INTER);
    transpose_split_kernel<<<dim3(CONV_DIM/32, DMODEL/32), 256>>>(
        W_xBC, p_Wc_hi + (size_t)XBC_OFF*DMODEL, p_Wc_lo + (size_t)XBC_OFF*DMODEL,
        DMODEL, CONV_DIM);
    transpose_split_pad_kernel<<<dim3(DTPAD/32, DMODEL/32), 256>>>(
        W_dt, p_Wc_hi + (size_t)DT_OFF*DMODEL, p_Wc_lo + (size_t)DT_OFF*DMODEL,
        DMODEL, NHEADS);
    // 1) fused input projection GEMM: [gate | xBC | dt]
    gemm_mma<<<dim3(NCAT/128, TOKENS/256), 256, GSMEM>>>(
        p_hs_hi, p_hs_lo, p_Wc_hi, p_Wc_lo, p_cat, TOKENS, NCAT, DMODEL);
    // 2) causal conv + silu, and softplus/dA precompute
    conv_silu_kernel<<<(TOKENS*CONV_DIM)/256, 256>>>(conv_w, conv_b);
    spdA_kernel<<<(TOKENS*NHEADS)/256, 256>>>(dt_bias, A_log);
    transpose_split_kernel<<<dim3(DMODEL/32, INTER/32), 256>>>(
        W_out, p_Wo_hi, p_Wo_lo, INTER, DMODEL);
    // 3) blocked SSM scan (packed f32x2)
    scan_kernel<<<BSZ*NHEADS, 256>>>(Dv);
    // 4) gated RMSNorm (+ split for out-proj)
    norm_kernel<<<TOKENS, 256>>>(norm_w);
    // 5) output projection
    gemm_mma<<<dim3(DMODEL/128, TOKENS/256), 256, GSMEM>>>(
        p_nm_hi, p_nm_lo, p_Wo_hi, p_Wo_lo, out, TOKENS, DMODEL, INTER);
    (void)n_in; (void)in_sizes; (void)out_size;
}